// round 2
// baseline (speedup 1.0000x reference)
#include <cuda_runtime.h>
#include <math.h>

#define HID 1024
#define LEN 40
#define VOC 50257

// ---- scratch (no allocations allowed) ----
__device__ float g_concat[3 * HID];  // [embedded ; attn_applied]
__device__ float g_x[HID];           // relu(comb) output
__device__ float g_hl0[HID];         // layer-0 hidden out
__device__ float g_hl1[HID];         // layer-1 hidden out
__device__ float g_lse[1];

__device__ __forceinline__ float warp_reduce(float s) {
#pragma unroll
    for (int o = 16; o; o >>= 1) s += __shfl_down_sync(0xFFFFFFFFu, s, o);
    return s;
}

// ---------------------------------------------------------------------------
// K1: embedding gather + attention logits + softmax + context (one block)
// ---------------------------------------------------------------------------
__global__ void __launch_bounds__(512)
k_attn(const int* __restrict__ tok,
       const float* __restrict__ h0,
       const float* __restrict__ emb,
       const float* __restrict__ attn_w,
       const float* __restrict__ attn_b,
       const float* __restrict__ enc,
       float* __restrict__ out_attnw) {
    __shared__ float s_ain[3 * HID];
    __shared__ float s_log[LEN];
    __shared__ float s_w[LEN];
    int t = threadIdx.x;            // 512 threads
    int token = tok[0];
    for (int i = t; i < HID; i += 512) {
        s_ain[i]           = emb[(size_t)token * HID + i];
        s_ain[HID + i]     = h0[i];
        s_ain[2 * HID + i] = h0[HID + i];
    }
    __syncthreads();

    int warp = t >> 5, lane = t & 31;   // 16 warps
    for (int l = warp; l < LEN; l += 16) {
        const float4* w = (const float4*)(attn_w + (size_t)l * 3 * HID);
        const float4* a = (const float4*)s_ain;
        float s = 0.f;
        for (int i = lane; i < 3 * HID / 4; i += 32) {
            float4 x = a[i], y = w[i];
            s += x.x * y.x + x.y * y.y + x.z * y.z + x.w * y.w;
        }
        s = warp_reduce(s);
        if (lane == 0) s_log[l] = s + attn_b[l];
    }
    __syncthreads();

    if (t == 0) {
        float m = s_log[0];
        for (int l = 1; l < LEN; l++) m = fmaxf(m, s_log[l]);
        float sum = 0.f;
        for (int l = 0; l < LEN; l++) { float e = expf(s_log[l] - m); s_w[l] = e; sum += e; }
        float inv = 1.f / sum;
        for (int l = 0; l < LEN; l++) { s_w[l] *= inv; out_attnw[l] = s_w[l]; }
    }
    __syncthreads();

    // attn_applied[j] = sum_l w[l] * enc[l, j], j in [0, 2H)
    for (int j = t; j < 2 * HID; j += 512) {
        float s = 0.f;
#pragma unroll
        for (int l = 0; l < LEN; l++) s += s_w[l] * enc[l * 2 * HID + j];
        g_concat[HID + j] = s;
    }
    for (int i = t; i < HID; i += 512) g_concat[i] = s_ain[i];   // embedded part
}

// ---------------------------------------------------------------------------
// K2: x = relu([emb;attn] @ comb_w.T + comb_b)  (1 warp / row, 1024 rows)
// ---------------------------------------------------------------------------
__global__ void __launch_bounds__(256)
k_comb(const float* __restrict__ comb_w,
       const float* __restrict__ comb_b) {
    int gw = (blockIdx.x * blockDim.x + threadIdx.x) >> 5;
    int lane = threadIdx.x & 31;
    if (gw >= HID) return;
    const float4* w = (const float4*)(comb_w + (size_t)gw * 3 * HID);
    const float4* v = (const float4*)g_concat;
    float s = 0.f;
#pragma unroll 4
    for (int i = lane; i < 3 * HID / 4; i += 32) {
        float4 a = v[i], b = w[i];
        s += a.x * b.x + a.y * b.y + a.z * b.z + a.w * b.w;
    }
    s = warp_reduce(s);
    if (lane == 0) g_x[gw] = fmaxf(s + comb_b[gw], 0.f);
}

// ---------------------------------------------------------------------------
// K3/K4: fused LSTM cell. 1 warp per hidden unit j; computes all 4 gates.
// layer=0: x=g_x, writes g_hl0.  layer=1: x=g_hl0, writes g_hl1.
// ---------------------------------------------------------------------------
__global__ void __launch_bounds__(256)
k_lstm(int layer,
       const float* __restrict__ hprev,
       const float* __restrict__ cprev,
       const float* __restrict__ w_ih,
       const float* __restrict__ w_hh,
       const float* __restrict__ b_ih,
       const float* __restrict__ b_hh,
       float* __restrict__ h_out,
       float* __restrict__ c_out) {
    __shared__ float s_x[HID];
    __shared__ float s_h[HID];
    const float* x = layer ? g_hl0 : g_x;
    for (int i = threadIdx.x; i < HID; i += blockDim.x) { s_x[i] = x[i]; s_h[i] = hprev[i]; }
    __syncthreads();

    int j = (blockIdx.x * blockDim.x + threadIdx.x) >> 5;
    int lane = threadIdx.x & 31;
    if (j >= HID) return;

    float g[4];
#pragma unroll
    for (int k = 0; k < 4; k++) {
        const float4* wi = (const float4*)(w_ih + (size_t)(k * HID + j) * HID);
        const float4* wh = (const float4*)(w_hh + (size_t)(k * HID + j) * HID);
        const float4* sx = (const float4*)s_x;
        const float4* sh = (const float4*)s_h;
        float s = 0.f;
#pragma unroll 4
        for (int i = lane; i < HID / 4; i += 32) {
            float4 a = sx[i], b = wi[i];
            s += a.x * b.x + a.y * b.y + a.z * b.z + a.w * b.w;
            float4 c = sh[i], d = wh[i];
            s += c.x * d.x + c.y * d.y + c.z * d.z + c.w * d.w;
        }
        g[k] = warp_reduce(s);
    }
    if (lane == 0) {
        float gi = g[0] + b_ih[j]           + b_hh[j];
        float gf = g[1] + b_ih[HID + j]     + b_hh[HID + j];
        float gg = g[2] + b_ih[2 * HID + j] + b_hh[2 * HID + j];
        float go = g[3] + b_ih[3 * HID + j] + b_hh[3 * HID + j];
        float si = 1.f / (1.f + expf(-gi));
        float sf = 1.f / (1.f + expf(-gf));
        float so = 1.f / (1.f + expf(-go));
        float c2 = sf * cprev[j] + si * tanhf(gg);
        float h2 = so * tanhf(c2);
        c_out[j] = c2;
        h_out[j] = h2;
        if (layer) g_hl1[j] = h2; else g_hl0[j] = h2;
    }
}

// ---------------------------------------------------------------------------
// K5: logits = h_l1 @ out_w.T + out_b   (1 warp / vocab row)
// ---------------------------------------------------------------------------
__global__ void __launch_bounds__(256)
k_logits(const float* __restrict__ out_w,
         const float* __restrict__ out_b,
         float* __restrict__ logits) {
    __shared__ float s_h[HID];
    for (int i = threadIdx.x; i < HID; i += blockDim.x) s_h[i] = g_hl1[i];
    __syncthreads();

    int r = (blockIdx.x * blockDim.x + threadIdx.x) >> 5;
    int lane = threadIdx.x & 31;
    if (r >= VOC) return;
    const float4* w = (const float4*)(out_w + (size_t)r * HID);
    const float4* v = (const float4*)s_h;
    float s = 0.f;
#pragma unroll 8
    for (int i = lane; i < HID / 4; i += 32) {
        float4 a = v[i], b = w[i];
        s += a.x * b.x + a.y * b.y + a.z * b.z + a.w * b.w;
    }
    s = warp_reduce(s);
    if (lane == 0) logits[r] = s + out_b[r];
}

// ---------------------------------------------------------------------------
// K6: log-sum-exp over vocab (single block)
// ---------------------------------------------------------------------------
__global__ void __launch_bounds__(512)
k_lse(const float* __restrict__ logits) {
    __shared__ float red[512];
    int t = threadIdx.x;
    float m = -INFINITY;
    for (int i = t; i < VOC; i += 512) m = fmaxf(m, logits[i]);
    red[t] = m;
    __syncthreads();
    for (int o = 256; o; o >>= 1) {
        if (t < o) red[t] = fmaxf(red[t], red[t + o]);
        __syncthreads();
    }
    m = red[0];
    __syncthreads();
    float s = 0.f;
    for (int i = t; i < VOC; i += 512) s += expf(logits[i] - m);
    red[t] = s;
    __syncthreads();
    for (int o = 256; o; o >>= 1) {
        if (t < o) red[t] += red[t + o];
        __syncthreads();
    }
    if (t == 0) g_lse[0] = m + logf(red[0]);
}

// K7: normalize in place
__global__ void __launch_bounds__(256)
k_sub(float* __restrict__ logits) {
    int i = blockIdx.x * blockDim.x + threadIdx.x;
    float lse = g_lse[0];
    if (i < VOC) logits[i] -= lse;
}

// ---------------------------------------------------------------------------
// Output layout: [log_probs(V) | h_new(2*H) | c_new(2*H) | attn_weights(L)]
// ---------------------------------------------------------------------------
extern "C" void kernel_launch(void* const* d_in, const int* in_sizes, int n_in,
                              void* d_out, int out_size) {
    const int*   tok    = (const int*)  d_in[0];
    const float* h0     = (const float*)d_in[1];   // [2,1,H]
    const float* c0     = (const float*)d_in[2];   // [2,1,H]
    const float* enc    = (const float*)d_in[3];   // [L, 2H]
    const float* emb    = (const float*)d_in[4];   // [V, H]
    const float* attn_w = (const float*)d_in[5];   // [L, 3H]
    const float* attn_b = (const float*)d_in[6];
    const float* comb_w = (const float*)d_in[7];   // [H, 3H]
    const float* comb_b = (const float*)d_in[8];
    const float* w_ih0  = (const float*)d_in[9];
    const float* w_hh0  = (const float*)d_in[10];
    const float* b_ih0  = (const float*)d_in[11];
    const float* b_hh0  = (const float*)d_in[12];
    const float* w_ih1  = (const float*)d_in[13];
    const float* w_hh1  = (const float*)d_in[14];
    const float* b_ih1  = (const float*)d_in[15];
    const float* b_hh1  = (const float*)d_in[16];
    const float* out_w  = (const float*)d_in[17];  // [V, H]
    const float* out_b  = (const float*)d_in[18];

    float* out      = (float*)d_out;
    float* o_logp   = out;                       // V
    float* o_h      = out + VOC;                 // 2H
    float* o_c      = out + VOC + 2 * HID;       // 2H
    float* o_attn   = out + VOC + 4 * HID;       // L

    k_attn<<<1, 512>>>(tok, h0, emb, attn_w, attn_b, enc, o_attn);
    k_comb<<<128, 256>>>(comb_w, comb_b);
    k_lstm<<<128, 256>>>(0, h0,       c0,       w_ih0, w_hh0, b_ih0, b_hh0,
                         o_h,       o_c);
    k_lstm<<<128, 256>>>(1, h0 + HID, c0 + HID, w_ih1, w_hh1, b_ih1, b_hh1,
                         o_h + HID, o_c + HID);
    k_logits<<<(VOC * 32 + 255) / 256, 256>>>(out_w, out_b, o_logp);
    k_lse<<<1, 512>>>(o_logp);
    k_sub<<<(VOC + 255) / 256, 256>>>(o_logp);
}

// round 3
// speedup vs baseline: 1.4021x; 1.4021x over previous
#include <cuda_runtime.h>
#include <math.h>

#define HID 1024
#define LEN 40
#define VOC 50257

// ---- scratch (no allocations allowed) ----
__device__ float g_concat[3 * HID];   // [embedded ; attn_applied]
__device__ float g_x[HID];            // relu(comb) output
__device__ float g_hl0[HID];          // layer-0 hidden out
__device__ float g_hl1[HID];          // layer-1 hidden out
__device__ float g_gates[4 * HID];    // gate pre-activations (reused per layer)
__device__ float g_lse[1];

__device__ __forceinline__ float warp_reduce(float s) {
#pragma unroll
    for (int o = 16; o; o >>= 1) s += __shfl_down_sync(0xFFFFFFFFu, s, o);
    return s;
}

__device__ __forceinline__ float dot4(float4 a, float4 b) {
    return a.x * b.x + a.y * b.y + a.z * b.z + a.w * b.w;
}

// ---------------------------------------------------------------------------
// K1: embedding gather + attention logits + softmax + context (one block)
// ---------------------------------------------------------------------------
__global__ void __launch_bounds__(512)
k_attn(const int* __restrict__ tok,
       const float* __restrict__ h0,
       const float* __restrict__ emb,
       const float* __restrict__ attn_w,
       const float* __restrict__ attn_b,
       const float* __restrict__ enc,
       float* __restrict__ out_attnw) {
    __shared__ float s_ain[3 * HID];
    __shared__ float s_log[LEN];
    __shared__ float s_w[LEN];
    int t = threadIdx.x;            // 512 threads
    int token = tok[0];
    for (int i = t; i < HID; i += 512) {
        s_ain[i]           = emb[(size_t)token * HID + i];
        s_ain[HID + i]     = h0[i];
        s_ain[2 * HID + i] = h0[HID + i];
    }
    __syncthreads();

    int warp = t >> 5, lane = t & 31;   // 16 warps
    for (int l = warp; l < LEN; l += 16) {
        const float4* w = (const float4*)(attn_w + (size_t)l * 3 * HID);
        const float4* a = (const float4*)s_ain;
        float s = 0.f;
        for (int i = lane; i < 3 * HID / 4; i += 32)
            s += dot4(a[i], __ldcs(&w[i]));
        s = warp_reduce(s);
        if (lane == 0) s_log[l] = s + attn_b[l];
    }
    __syncthreads();

    if (t == 0) {
        float m = s_log[0];
        for (int l = 1; l < LEN; l++) m = fmaxf(m, s_log[l]);
        float sum = 0.f;
        for (int l = 0; l < LEN; l++) { float e = expf(s_log[l] - m); s_w[l] = e; sum += e; }
        float inv = 1.f / sum;
        for (int l = 0; l < LEN; l++) { s_w[l] *= inv; out_attnw[l] = s_w[l]; }
    }
    __syncthreads();

    // attn_applied[j] = sum_l w[l] * enc[l, j], j in [0, 2H)
    for (int j = t; j < 2 * HID; j += 512) {
        float s = 0.f;
#pragma unroll
        for (int l = 0; l < LEN; l++) s += s_w[l] * enc[l * 2 * HID + j];
        g_concat[HID + j] = s;
    }
    for (int i = t; i < HID; i += 512) g_concat[i] = s_ain[i];   // embedded part
}

// ---------------------------------------------------------------------------
// K2: x = relu([emb;attn] @ comb_w.T + comb_b)  — one block (4 warps) per row
// ---------------------------------------------------------------------------
__global__ void __launch_bounds__(128)
k_comb(const float* __restrict__ comb_w,
       const float* __restrict__ comb_b) {
    __shared__ float s_part[4];
    int row = blockIdx.x;               // 1024 rows
    int t = threadIdx.x;                // 128 threads
    int warp = t >> 5, lane = t & 31;
    const float4* w = (const float4*)(comb_w + (size_t)row * 3 * HID);
    const float4* v = (const float4*)g_concat;
    float s = 0.f;
#pragma unroll
    for (int i = t; i < 3 * HID / 4; i += 128)   // 6 iters per thread
        s += dot4(v[i], __ldcs(&w[i]));
    s = warp_reduce(s);
    if (lane == 0) s_part[warp] = s;
    __syncthreads();
    if (t == 0)
        g_x[row] = fmaxf(s_part[0] + s_part[1] + s_part[2] + s_part[3]
                         + comb_b[row], 0.f);
}

// ---------------------------------------------------------------------------
// K3a: LSTM gate matvecs. One warp per (gate,unit) row: 4096 warps.
// row r in [0,4H): g_gates[r] = w_ih[r,:]·x + w_hh[r,:]·hprev
// ---------------------------------------------------------------------------
__global__ void __launch_bounds__(256)
k_gates(int layer,
        const float* __restrict__ hprev,
        const float* __restrict__ w_ih,
        const float* __restrict__ w_hh) {
    __shared__ float s_x[HID];
    __shared__ float s_h[HID];
    const float* x = layer ? g_hl0 : g_x;
    for (int i = threadIdx.x; i < HID; i += 256) { s_x[i] = x[i]; s_h[i] = hprev[i]; }
    __syncthreads();

    int r = (blockIdx.x * 256 + threadIdx.x) >> 5;   // 0..4095
    int lane = threadIdx.x & 31;
    const float4* wi = (const float4*)(w_ih + (size_t)r * HID);
    const float4* wh = (const float4*)(w_hh + (size_t)r * HID);
    const float4* sx = (const float4*)s_x;
    const float4* sh = (const float4*)s_h;
    float s = 0.f;
#pragma unroll
    for (int i = lane; i < HID / 4; i += 32) {       // 8 iters, fully unrolled
        s += dot4(sx[i], __ldcs(&wi[i]));
        s += dot4(sh[i], __ldcs(&wh[i]));
    }
    s = warp_reduce(s);
    if (lane == 0) g_gates[r] = s;
}

// ---------------------------------------------------------------------------
// K3b: LSTM elementwise combine (1 block, 1024 threads)
// ---------------------------------------------------------------------------
__global__ void __launch_bounds__(1024, 1)
k_elem(int layer,
       const float* __restrict__ cprev,
       const float* __restrict__ b_ih,
       const float* __restrict__ b_hh,
       float* __restrict__ h_out,
       float* __restrict__ c_out) {
    int j = threadIdx.x;
    float gi = g_gates[j]           + b_ih[j]           + b_hh[j];
    float gf = g_gates[HID + j]     + b_ih[HID + j]     + b_hh[HID + j];
    float gg = g_gates[2 * HID + j] + b_ih[2 * HID + j] + b_hh[2 * HID + j];
    float go = g_gates[3 * HID + j] + b_ih[3 * HID + j] + b_hh[3 * HID + j];
    float si = 1.f / (1.f + expf(-gi));
    float sf = 1.f / (1.f + expf(-gf));
    float so = 1.f / (1.f + expf(-go));
    float c2 = sf * cprev[j] + si * tanhf(gg);
    float h2 = so * tanhf(c2);
    c_out[j] = c2;
    h_out[j] = h2;
    if (layer) g_hl1[j] = h2; else g_hl0[j] = h2;
}

// ---------------------------------------------------------------------------
// K5: logits = h_l1 @ out_w.T + out_b   (1 warp / vocab row)
// ---------------------------------------------------------------------------
__global__ void __launch_bounds__(256)
k_logits(const float* __restrict__ out_w,
         const float* __restrict__ out_b,
         float* __restrict__ logits) {
    __shared__ float s_h[HID];
    for (int i = threadIdx.x; i < HID; i += 256) s_h[i] = g_hl1[i];
    __syncthreads();

    int r = (blockIdx.x * 256 + threadIdx.x) >> 5;
    int lane = threadIdx.x & 31;
    if (r >= VOC) return;
    const float4* w = (const float4*)(out_w + (size_t)r * HID);
    const float4* v = (const float4*)s_h;
    float s = 0.f;
#pragma unroll
    for (int i = lane; i < HID / 4; i += 32)    // 8 iters, fully unrolled
        s += dot4(v[i], __ldcs(&w[i]));
    s = warp_reduce(s);
    if (lane == 0) logits[r] = s + out_b[r];
}

// ---------------------------------------------------------------------------
// K6: log-sum-exp over vocab (single block)
// ---------------------------------------------------------------------------
__global__ void __launch_bounds__(512)
k_lse(const float* __restrict__ logits) {
    __shared__ float red[512];
    int t = threadIdx.x;
    float m = -INFINITY;
    for (int i = t; i < VOC; i += 512) m = fmaxf(m, logits[i]);
    red[t] = m;
    __syncthreads();
    for (int o = 256; o; o >>= 1) {
        if (t < o) red[t] = fmaxf(red[t], red[t + o]);
        __syncthreads();
    }
    m = red[0];
    __syncthreads();
    float s = 0.f;
    for (int i = t; i < VOC; i += 512) s += expf(logits[i] - m);
    red[t] = s;
    __syncthreads();
    for (int o = 256; o; o >>= 1) {
        if (t < o) red[t] += red[t + o];
        __syncthreads();
    }
    if (t == 0) g_lse[0] = m + logf(red[0]);
}

// K7: normalize in place
__global__ void __launch_bounds__(256)
k_sub(float* __restrict__ logits) {
    int i = blockIdx.x * blockDim.x + threadIdx.x;
    float lse = g_lse[0];
    if (i < VOC) logits[i] -= lse;
}

// ---------------------------------------------------------------------------
// Output layout: [log_probs(V) | h_new(2*H) | c_new(2*H) | attn_weights(L)]
// ---------------------------------------------------------------------------
extern "C" void kernel_launch(void* const* d_in, const int* in_sizes, int n_in,
                              void* d_out, int out_size) {
    const int*   tok    = (const int*)  d_in[0];
    const float* h0     = (const float*)d_in[1];   // [2,1,H]
    const float* c0     = (const float*)d_in[2];   // [2,1,H]
    const float* enc    = (const float*)d_in[3];   // [L, 2H]
    const float* emb    = (const float*)d_in[4];   // [V, H]
    const float* attn_w = (const float*)d_in[5];   // [L, 3H]
    const float* attn_b = (const float*)d_in[6];
    const float* comb_w = (const float*)d_in[7];   // [H, 3H]
    const float* comb_b = (const float*)d_in[8];
    const float* w_ih0  = (const float*)d_in[9];
    const float* w_hh0  = (const float*)d_in[10];
    const float* b_ih0  = (const float*)d_in[11];
    const float* b_hh0  = (const float*)d_in[12];
    const float* w_ih1  = (const float*)d_in[13];
    const float* w_hh1  = (const float*)d_in[14];
    const float* b_ih1  = (const float*)d_in[15];
    const float* b_hh1  = (const float*)d_in[16];
    const float* out_w  = (const float*)d_in[17];  // [V, H]
    const float* out_b  = (const float*)d_in[18];

    float* out      = (float*)d_out;
    float* o_logp   = out;                       // V
    float* o_h      = out + VOC;                 // 2H
    float* o_c      = out + VOC + 2 * HID;       // 2H
    float* o_attn   = out + VOC + 4 * HID;       // L

    k_attn<<<1, 512>>>(tok, h0, emb, attn_w, attn_b, enc, o_attn);
    k_comb<<<1024, 128>>>(comb_w, comb_b);
    k_gates<<<512, 256>>>(0, h0,       w_ih0, w_hh0);
    k_elem<<<1, 1024>>>(0, c0,       b_ih0, b_hh0, o_h,       o_c);
    k_gates<<<512, 256>>>(1, h0 + HID, w_ih1, w_hh1);
    k_elem<<<1, 1024>>>(1, c0 + HID, b_ih1, b_hh1, o_h + HID, o_c + HID);
    k_logits<<<(VOC * 32 + 255) / 256, 256>>>(out_w, out_b, o_logp);
    k_lse<<<1, 512>>>(o_logp);
    k_sub<<<(VOC + 255) / 256, 256>>>(o_logp);
}

// round 4
// speedup vs baseline: 1.4278x; 1.0183x over previous
#include <cuda_runtime.h>
#include <math.h>

#define HID 1024
#define LEN 40
#define VOC 50257

// ---- scratch (no allocations allowed) ----
__device__ float g_concat[3 * HID];   // [embedded ; attn_applied]
__device__ float g_x[HID];            // relu(comb) output
__device__ float g_hl0[HID];          // layer-0 hidden out
__device__ float g_hl1[HID];          // layer-1 hidden out
__device__ float g_lse[1];

__device__ __forceinline__ float warp_reduce(float s) {
#pragma unroll
    for (int o = 16; o; o >>= 1) s += __shfl_down_sync(0xFFFFFFFFu, s, o);
    return s;
}

__device__ __forceinline__ float dot4(float4 a, float4 b) {
    return a.x * b.x + a.y * b.y + a.z * b.z + a.w * b.w;
}

// ---------------------------------------------------------------------------
// K1: embedding gather + attention logits + softmax + context (one block)
// ---------------------------------------------------------------------------
__global__ void __launch_bounds__(512)
k_attn(const int* __restrict__ tok,
       const float* __restrict__ h0,
       const float* __restrict__ emb,
       const float* __restrict__ attn_w,
       const float* __restrict__ attn_b,
       const float* __restrict__ enc,
       float* __restrict__ out_attnw) {
    __shared__ float s_ain[3 * HID];
    __shared__ float s_log[LEN];
    __shared__ float s_w[LEN];
    int t = threadIdx.x;            // 512 threads
    int token = tok[0];
    for (int i = t; i < HID; i += 512) {
        s_ain[i]           = emb[(size_t)token * HID + i];
        s_ain[HID + i]     = h0[i];
        s_ain[2 * HID + i] = h0[HID + i];
    }
    __syncthreads();

    int warp = t >> 5, lane = t & 31;   // 16 warps
    for (int l = warp; l < LEN; l += 16) {
        const float4* w = (const float4*)(attn_w + (size_t)l * 3 * HID);
        const float4* a = (const float4*)s_ain;
        float s = 0.f;
        for (int i = lane; i < 3 * HID / 4; i += 32)
            s += dot4(a[i], __ldcs(&w[i]));
        s = warp_reduce(s);
        if (lane == 0) s_log[l] = s + attn_b[l];
    }
    __syncthreads();

    if (t == 0) {
        float m = s_log[0];
        for (int l = 1; l < LEN; l++) m = fmaxf(m, s_log[l]);
        float sum = 0.f;
        for (int l = 0; l < LEN; l++) { float e = expf(s_log[l] - m); s_w[l] = e; sum += e; }
        float inv = 1.f / sum;
        for (int l = 0; l < LEN; l++) { s_w[l] *= inv; out_attnw[l] = s_w[l]; }
    }
    __syncthreads();

    // attn_applied[j] = sum_l w[l] * enc[l, j], j in [0, 2H)
    for (int j = t; j < 2 * HID; j += 512) {
        float s = 0.f;
#pragma unroll
        for (int l = 0; l < LEN; l++) s += s_w[l] * enc[l * 2 * HID + j];
        g_concat[HID + j] = s;
    }
    for (int i = t; i < HID; i += 512) g_concat[i] = s_ain[i];   // embedded part
}

// ---------------------------------------------------------------------------
// K2: x = relu([emb;attn] @ comb_w.T + comb_b)  — one block (4 warps) per row
// ---------------------------------------------------------------------------
__global__ void __launch_bounds__(128)
k_comb(const float* __restrict__ comb_w,
       const float* __restrict__ comb_b) {
    __shared__ float s_part[4];
    int row = blockIdx.x;               // 1024 rows
    int t = threadIdx.x;                // 128 threads
    int warp = t >> 5, lane = t & 31;
    const float4* w = (const float4*)(comb_w + (size_t)row * 3 * HID);
    const float4* v = (const float4*)g_concat;
    float s = 0.f;
#pragma unroll
    for (int i = t; i < 3 * HID / 4; i += 128)   // 6 iters per thread
        s += dot4(v[i], __ldcs(&w[i]));
    s = warp_reduce(s);
    if (lane == 0) s_part[warp] = s;
    __syncthreads();
    if (t == 0)
        g_x[row] = fmaxf(s_part[0] + s_part[1] + s_part[2] + s_part[3]
                         + comb_b[row], 0.f);
}

// ---------------------------------------------------------------------------
// K3: fused LSTM cell. One block per hidden unit (1024 blocks x 128 threads).
// Warp k computes gate k's full pre-activation; thread 0 combines.
// ---------------------------------------------------------------------------
__global__ void __launch_bounds__(128)
k_lstm(int layer,
       const float* __restrict__ hprev,
       const float* __restrict__ cprev,
       const float* __restrict__ w_ih,
       const float* __restrict__ w_hh,
       const float* __restrict__ b_ih,
       const float* __restrict__ b_hh,
       float* __restrict__ h_out,
       float* __restrict__ c_out) {
    __shared__ float s_x[HID];
    __shared__ float s_h[HID];
    __shared__ float s_g[4];
    const float* x = layer ? g_hl0 : g_x;
    int t = threadIdx.x;
    for (int i = t; i < HID; i += 128) { s_x[i] = x[i]; s_h[i] = hprev[i]; }
    __syncthreads();

    int u = blockIdx.x;                 // hidden unit
    int warp = t >> 5, lane = t & 31;   // warp = gate index (i,f,g,o)
    int r = warp * HID + u;             // weight row
    const float4* wi = (const float4*)(w_ih + (size_t)r * HID);
    const float4* wh = (const float4*)(w_hh + (size_t)r * HID);
    const float4* sx = (const float4*)s_x;
    const float4* sh = (const float4*)s_h;
    float s = 0.f;
#pragma unroll
    for (int i = lane; i < HID / 4; i += 32) {   // 8 iters x2 streams, unrolled
        s += dot4(sx[i], __ldcs(&wi[i]));
        s += dot4(sh[i], __ldcs(&wh[i]));
    }
    s = warp_reduce(s);
    if (lane == 0) s_g[warp] = s + b_ih[r] + b_hh[r];
    __syncthreads();

    if (t == 0) {
        float gi = s_g[0], gf = s_g[1], gg = s_g[2], go = s_g[3];
        float si = 1.f / (1.f + expf(-gi));
        float sf = 1.f / (1.f + expf(-gf));
        float so = 1.f / (1.f + expf(-go));
        float c2 = sf * cprev[u] + si * tanhf(gg);
        float h2 = so * tanhf(c2);
        c_out[u] = c2;
        h_out[u] = h2;
        if (layer) g_hl1[u] = h2; else g_hl0[u] = h2;
    }
}

// ---------------------------------------------------------------------------
// K5: logits = h_l1 @ out_w.T + out_b   (1 warp / vocab row)
// ---------------------------------------------------------------------------
__global__ void __launch_bounds__(256)
k_logits(const float* __restrict__ out_w,
         const float* __restrict__ out_b,
         float* __restrict__ logits) {
    __shared__ float s_h[HID];
    for (int i = threadIdx.x; i < HID; i += 256) s_h[i] = g_hl1[i];
    __syncthreads();

    int r = (blockIdx.x * 256 + threadIdx.x) >> 5;
    int lane = threadIdx.x & 31;
    if (r >= VOC) return;
    const float4* w = (const float4*)(out_w + (size_t)r * HID);
    const float4* v = (const float4*)s_h;
    float s = 0.f;
#pragma unroll
    for (int i = lane; i < HID / 4; i += 32)    // 8 iters, fully unrolled
        s += dot4(v[i], __ldcs(&w[i]));
    s = warp_reduce(s);
    if (lane == 0) logits[r] = s + out_b[r];
}

// ---------------------------------------------------------------------------
// K6: log-sum-exp over vocab (single block, 1024 threads)
// ---------------------------------------------------------------------------
__global__ void __launch_bounds__(1024, 1)
k_lse(const float* __restrict__ logits) {
    __shared__ float red[1024];
    int t = threadIdx.x;
    float m = -INFINITY;
    for (int i = t; i < VOC; i += 1024) m = fmaxf(m, logits[i]);
    red[t] = m;
    __syncthreads();
    for (int o = 512; o; o >>= 1) {
        if (t < o) red[t] = fmaxf(red[t], red[t + o]);
        __syncthreads();
    }
    m = red[0];
    __syncthreads();
    float s = 0.f;
    for (int i = t; i < VOC; i += 1024) s += expf(logits[i] - m);
    red[t] = s;
    __syncthreads();
    for (int o = 512; o; o >>= 1) {
        if (t < o) red[t] += red[t + o];
        __syncthreads();
    }
    if (t == 0) g_lse[0] = m + logf(red[0]);
}

// K7: normalize in place
__global__ void __launch_bounds__(256)
k_sub(float* __restrict__ logits) {
    int i = blockIdx.x * blockDim.x + threadIdx.x;
    float lse = g_lse[0];
    if (i < VOC) logits[i] -= lse;
}

// ---------------------------------------------------------------------------
// Output layout: [log_probs(V) | h_new(2*H) | c_new(2*H) | attn_weights(L)]
// ---------------------------------------------------------------------------
extern "C" void kernel_launch(void* const* d_in, const int* in_sizes, int n_in,
                              void* d_out, int out_size) {
    const int*   tok    = (const int*)  d_in[0];
    const float* h0     = (const float*)d_in[1];   // [2,1,H]
    const float* c0     = (const float*)d_in[2];   // [2,1,H]
    const float* enc    = (const float*)d_in[3];   // [L, 2H]
    const float* emb    = (const float*)d_in[4];   // [V, H]
    const float* attn_w = (const float*)d_in[5];   // [L, 3H]
    const float* attn_b = (const float*)d_in[6];
    const float* comb_w = (const float*)d_in[7];   // [H, 3H]
    const float* comb_b = (const float*)d_in[8];
    const float* w_ih0  = (const float*)d_in[9];
    const float* w_hh0  = (const float*)d_in[10];
    const float* b_ih0  = (const float*)d_in[11];
    const float* b_hh0  = (const float*)d_in[12];
    const float* w_ih1  = (const float*)d_in[13];
    const float* w_hh1  = (const float*)d_in[14];
    const float* b_ih1  = (const float*)d_in[15];
    const float* b_hh1  = (const float*)d_in[16];
    const float* out_w  = (const float*)d_in[17];  // [V, H]
    const float* out_b  = (const float*)d_in[18];

    float* out      = (float*)d_out;
    float* o_logp   = out;                       // V
    float* o_h      = out + VOC;                 // 2H
    float* o_c      = out + VOC + 2 * HID;       // 2H
    float* o_attn   = out + VOC + 4 * HID;       // L

    k_attn<<<1, 512>>>(tok, h0, emb, attn_w, attn_b, enc, o_attn);
    k_comb<<<1024, 128>>>(comb_w, comb_b);
    k_lstm<<<1024, 128>>>(0, h0,       c0,       w_ih0, w_hh0, b_ih0, b_hh0,
                          o_h,       o_c);
    k_lstm<<<1024, 128>>>(1, h0 + HID, c0 + HID, w_ih1, w_hh1, b_ih1, b_hh1,
                          o_h + HID, o_c + HID);
    k_logits<<<(VOC * 32 + 255) / 256, 256>>>(out_w, out_b, o_logp);
    k_lse<<<1, 1024>>>(o_logp);
    k_sub<<<(VOC + 255) / 256, 256>>>(o_logp);
}

// round 5
// speedup vs baseline: 1.5369x; 1.0764x over previous
#include <cuda_runtime.h>
#include <math.h>

#define HID 1024
#define LEN 40
#define VOC 50257
#define NPART 6283   // ceil(VOC/8)

// ---- scratch (no allocations allowed) ----
__device__ float g_concat[3 * HID];   // [embedded ; attn_applied]
__device__ float g_x[HID];            // relu(comb) output
__device__ float g_hl0[HID];          // layer-0 hidden out
__device__ float g_hl1[HID];          // layer-1 hidden out
__device__ float g_pm[NPART];         // per-block logit max
__device__ float g_ps[NPART];         // per-block expsum
__device__ float g_lse[1];

__device__ __forceinline__ float warp_reduce(float s) {
#pragma unroll
    for (int o = 16; o; o >>= 1) s += __shfl_down_sync(0xFFFFFFFFu, s, o);
    return s;
}

__device__ __forceinline__ float dot4(float4 a, float4 b) {
    return a.x * b.x + a.y * b.y + a.z * b.z + a.w * b.w;
}

// ---------------------------------------------------------------------------
// K1: embedding gather + attention logits + softmax + context (one block)
// ---------------------------------------------------------------------------
__global__ void __launch_bounds__(512)
k_attn(const int* __restrict__ tok,
       const float* __restrict__ h0,
       const float* __restrict__ emb,
       const float* __restrict__ attn_w,
       const float* __restrict__ attn_b,
       const float* __restrict__ enc,
       float* __restrict__ out_attnw) {
    __shared__ float s_ain[3 * HID];
    __shared__ float s_log[LEN];
    __shared__ float s_w[LEN];
    int t = threadIdx.x;            // 512 threads
    int token = tok[0];
    for (int i = t; i < HID; i += 512) {
        s_ain[i]           = emb[(size_t)token * HID + i];
        s_ain[HID + i]     = h0[i];
        s_ain[2 * HID + i] = h0[HID + i];
    }
    __syncthreads();

    int warp = t >> 5, lane = t & 31;   // 16 warps
    for (int l = warp; l < LEN; l += 16) {
        const float4* w = (const float4*)(attn_w + (size_t)l * 3 * HID);
        const float4* a = (const float4*)s_ain;
        float4 wr[8];
        float s = 0.f;
#pragma unroll
        for (int k = 0; k < 8; k++) wr[k] = __ldcs(&w[lane + 32 * k]);
#pragma unroll
        for (int k = 0; k < 8; k++) s += dot4(a[lane + 32 * k], wr[k]);
#pragma unroll
        for (int k = 8; k < 16; k++) wr[k - 8] = __ldcs(&w[lane + 32 * k]);
#pragma unroll
        for (int k = 8; k < 16; k++) s += dot4(a[lane + 32 * k], wr[k - 8]);
#pragma unroll
        for (int k = 16; k < 24; k++) wr[k - 16] = __ldcs(&w[lane + 32 * k]);
#pragma unroll
        for (int k = 16; k < 24; k++) s += dot4(a[lane + 32 * k], wr[k - 16]);
        s = warp_reduce(s);
        if (lane == 0) s_log[l] = s + attn_b[l];
    }
    __syncthreads();

    if (t == 0) {
        float m = s_log[0];
        for (int l = 1; l < LEN; l++) m = fmaxf(m, s_log[l]);
        float sum = 0.f;
        for (int l = 0; l < LEN; l++) { float e = expf(s_log[l] - m); s_w[l] = e; sum += e; }
        float inv = 1.f / sum;
        for (int l = 0; l < LEN; l++) { s_w[l] *= inv; out_attnw[l] = s_w[l]; }
    }
    __syncthreads();

    // attn_applied[j] = sum_l w[l] * enc[l, j], j in [0, 2H)
    for (int j = t; j < 2 * HID; j += 512) {
        float s = 0.f;
#pragma unroll
        for (int l = 0; l < LEN; l++) s += s_w[l] * enc[l * 2 * HID + j];
        g_concat[HID + j] = s;
    }
    for (int i = t; i < HID; i += 512) g_concat[i] = s_ain[i];   // embedded part
}

// ---------------------------------------------------------------------------
// K2: x = relu([emb;attn] @ comb_w.T + comb_b) — block per row, batched loads
// ---------------------------------------------------------------------------
__global__ void __launch_bounds__(128)
k_comb(const float* __restrict__ comb_w,
       const float* __restrict__ comb_b) {
    __shared__ float s_part[4];
    int row = blockIdx.x;               // 1024 rows
    int t = threadIdx.x;                // 128 threads
    int warp = t >> 5, lane = t & 31;
    const float4* w = (const float4*)(comb_w + (size_t)row * 3 * HID);
    const float4* v = (const float4*)g_concat;
    float4 wr[6];
#pragma unroll
    for (int k = 0; k < 6; k++) wr[k] = __ldcs(&w[t + 128 * k]);
    float s = 0.f;
#pragma unroll
    for (int k = 0; k < 6; k++) s += dot4(v[t + 128 * k], wr[k]);
    s = warp_reduce(s);
    if (lane == 0) s_part[warp] = s;
    __syncthreads();
    if (t == 0)
        g_x[row] = fmaxf(s_part[0] + s_part[1] + s_part[2] + s_part[3]
                         + comb_b[row], 0.f);
}

// ---------------------------------------------------------------------------
// K3: fused LSTM cell. Warp per (unit,gate): 512 blocks x 256 thr = 4096 warps.
// Block covers 2 units (warps 0-3: unit0 gates i,f,g,o; warps 4-7: unit1).
// ---------------------------------------------------------------------------
__global__ void __launch_bounds__(256)
k_lstm(int layer,
       const float* __restrict__ hprev,
       const float* __restrict__ cprev,
       const float* __restrict__ w_ih,
       const float* __restrict__ w_hh,
       const float* __restrict__ b_ih,
       const float* __restrict__ b_hh,
       float* __restrict__ h_out,
       float* __restrict__ c_out) {
    __shared__ float s_g[8];
    int t = threadIdx.x;
    int wid = t >> 5, lane = t & 31;
    int uu = wid >> 2;                    // 0..1 unit within block
    int gate = wid & 3;                   // 0..3 (i,f,g,o)
    int u = blockIdx.x * 2 + uu;          // hidden unit
    int row = gate * HID + u;             // weight row

    const float4* wi = (const float4*)(w_ih + (size_t)row * HID);
    const float4* wh = (const float4*)(w_hh + (size_t)row * HID);
    const float4* x4 = (const float4*)(layer ? g_hl0 : g_x);
    const float4* h4 = (const float4*)hprev;

    float4 wr[8];
    float s = 0.f;
#pragma unroll
    for (int k = 0; k < 8; k++) wr[k] = __ldcs(&wi[lane + 32 * k]);
#pragma unroll
    for (int k = 0; k < 8; k++) s += dot4(x4[lane + 32 * k], wr[k]);
#pragma unroll
    for (int k = 0; k < 8; k++) wr[k] = __ldcs(&wh[lane + 32 * k]);
#pragma unroll
    for (int k = 0; k < 8; k++) s += dot4(h4[lane + 32 * k], wr[k]);
    s = warp_reduce(s);
    if (lane == 0) s_g[wid] = s + b_ih[row] + b_hh[row];
    __syncthreads();

    if (t < 2) {
        int u2 = blockIdx.x * 2 + t;
        int b = t * 4;
        float gi = s_g[b + 0], gf = s_g[b + 1], gg = s_g[b + 2], go = s_g[b + 3];
        float si = 1.f / (1.f + expf(-gi));
        float sf = 1.f / (1.f + expf(-gf));
        float so = 1.f / (1.f + expf(-go));
        float c2 = sf * cprev[u2] + si * tanhf(gg);
        float h2 = so * tanhf(c2);
        c_out[u2] = c2;
        h_out[u2] = h2;
        if (layer) g_hl1[u2] = h2; else g_hl0[u2] = h2;
    }
}

// ---------------------------------------------------------------------------
// K5: logits = h_l1 @ out_w.T + out_b (warp per row) + per-block lse partials
// ---------------------------------------------------------------------------
__global__ void __launch_bounds__(256)
k_logits(const float* __restrict__ out_w,
         const float* __restrict__ out_b,
         float* __restrict__ logits) {
    __shared__ float s_l[8];
    int t = threadIdx.x;
    int wid = t >> 5, lane = t & 31;
    int r = blockIdx.x * 8 + wid;

    if (r < VOC) {
        const float4* w = (const float4*)(out_w + (size_t)r * HID);
        const float4* h4 = (const float4*)g_hl1;
        float4 wr[8];
        float s = 0.f;
#pragma unroll
        for (int k = 0; k < 8; k++) wr[k] = __ldcs(&w[lane + 32 * k]);
#pragma unroll
        for (int k = 0; k < 8; k++) s += dot4(h4[lane + 32 * k], wr[k]);
        s = warp_reduce(s);
        if (lane == 0) {
            float lg = s + out_b[r];
            logits[r] = lg;
            s_l[wid] = lg;
        }
    } else if (lane == 0) {
        s_l[wid] = -INFINITY;
    }
    __syncthreads();

    if (t == 0) {
        float m = s_l[0];
#pragma unroll
        for (int k = 1; k < 8; k++) m = fmaxf(m, s_l[k]);
        float sum = 0.f;
#pragma unroll
        for (int k = 0; k < 8; k++) sum += expf(s_l[k] - m);
        g_pm[blockIdx.x] = m;
        g_ps[blockIdx.x] = sum;
    }
}

// ---------------------------------------------------------------------------
// K6: combine per-block partials into log-sum-exp (single block)
// ---------------------------------------------------------------------------
__global__ void __launch_bounds__(1024, 1)
k_lse(void) {
    __shared__ float red[1024];
    int t = threadIdx.x;
    float m = -INFINITY;
    for (int i = t; i < NPART; i += 1024) m = fmaxf(m, g_pm[i]);
    red[t] = m;
    __syncthreads();
    for (int o = 512; o; o >>= 1) {
        if (t < o) red[t] = fmaxf(red[t], red[t + o]);
        __syncthreads();
    }
    m = red[0];
    __syncthreads();
    float s = 0.f;
    for (int i = t; i < NPART; i += 1024) s += g_ps[i] * expf(g_pm[i] - m);
    red[t] = s;
    __syncthreads();
    for (int o = 512; o; o >>= 1) {
        if (t < o) red[t] += red[t + o];
        __syncthreads();
    }
    if (t == 0) g_lse[0] = m + logf(red[0]);
}

// K7: normalize in place
__global__ void __launch_bounds__(256)
k_sub(float* __restrict__ logits) {
    int i = blockIdx.x * blockDim.x + threadIdx.x;
    float lse = g_lse[0];
    if (i < VOC) logits[i] -= lse;
}

// ---------------------------------------------------------------------------
// Output layout: [log_probs(V) | h_new(2*H) | c_new(2*H) | attn_weights(L)]
// ---------------------------------------------------------------------------
extern "C" void kernel_launch(void* const* d_in, const int* in_sizes, int n_in,
                              void* d_out, int out_size) {
    const int*   tok    = (const int*)  d_in[0];
    const float* h0     = (const float*)d_in[1];   // [2,1,H]
    const float* c0     = (const float*)d_in[2];   // [2,1,H]
    const float* enc    = (const float*)d_in[3];   // [L, 2H]
    const float* emb    = (const float*)d_in[4];   // [V, H]
    const float* attn_w = (const float*)d_in[5];   // [L, 3H]
    const float* attn_b = (const float*)d_in[6];
    const float* comb_w = (const float*)d_in[7];   // [H, 3H]
    const float* comb_b = (const float*)d_in[8];
    const float* w_ih0  = (const float*)d_in[9];
    const float* w_hh0  = (const float*)d_in[10];
    const float* b_ih0  = (const float*)d_in[11];
    const float* b_hh0  = (const float*)d_in[12];
    const float* w_ih1  = (const float*)d_in[13];
    const float* w_hh1  = (const float*)d_in[14];
    const float* b_ih1  = (const float*)d_in[15];
    const float* b_hh1  = (const float*)d_in[16];
    const float* out_w  = (const float*)d_in[17];  // [V, H]
    const float* out_b  = (const float*)d_in[18];

    float* out      = (float*)d_out;
    float* o_logp   = out;                       // V
    float* o_h      = out + VOC;                 // 2H
    float* o_c      = out + VOC + 2 * HID;       // 2H
    float* o_attn   = out + VOC + 4 * HID;       // L

    k_attn<<<1, 512>>>(tok, h0, emb, attn_w, attn_b, enc, o_attn);
    k_comb<<<1024, 128>>>(comb_w, comb_b);
    k_lstm<<<512, 256>>>(0, h0,       c0,       w_ih0, w_hh0, b_ih0, b_hh0,
                         o_h,       o_c);
    k_lstm<<<512, 256>>>(1, h0 + HID, c0 + HID, w_ih1, w_hh1, b_ih1, b_hh1,
                         o_h + HID, o_c + HID);
    k_logits<<<NPART, 256>>>(out_w, out_b, o_logp);
    k_lse<<<1, 1024>>>();
    k_sub<<<(VOC + 255) / 256, 256>>>(o_logp);
}